// round 1
// baseline (speedup 1.0000x reference)
#include <cuda_runtime.h>
#include <cuda_bf16.h>

// Problem dims (fixed by reference)
#define Bdim   8
#define Ndim   32
#define Cdim   768
#define Tdim   256
#define Pdim   16
#define KTOP   5
#define BNprod (Bdim * Ndim)   // 256

// Output layout (float32, concatenated in return-tuple order)
#define OFF_ID      0            // id_src        (B,K)        = 40
#define OFF_SCORE   40           // score_src     (B,K)        = 40
#define OFF_SPTS    80           // score_pts     (B,K,T)      = 10240
#define OFF_TAR     10320        // tar_pts       (B,K,T,2)    = 20480
#define OFF_SRC     30800        // src_pts       (B,K,T,2)    = 20480
#define OFF_CNT     51280        // match_counts  (B,N)        = 256
// total 51536

// Scratch (no cudaMalloc allowed)
__device__ unsigned long long g_t2s[BNprod * Tdim];   // packed (score, ~argmax_s) per (b,n,t)
__device__ unsigned long long g_s2t[BNprod * Tdim];   // packed (score, ~argmax_t) per (b,n,s)
__device__ float              g_mask_all[BNprod * Tdim];
__device__ float              g_simavg[BNprod];
__device__ int                g_sel[Bdim * KTOP];

#define INIT_PACK 0x00000000FFFFFFFFULL   // score=0.0, idx=0

static __device__ __forceinline__ unsigned long long fma2(unsigned long long a,
                                                          unsigned long long b,
                                                          unsigned long long c) {
    unsigned long long d;
    asm("fma.rn.f32x2 %0, %1, %2, %3;" : "=l"(d) : "l"(a), "l"(b), "l"(c));
    return d;
}
static __device__ __forceinline__ unsigned long long dup2(float x) {
    unsigned long long r;
    asm("mov.b64 %0, {%1, %1};" : "=l"(r) : "f"(x));
    return r;
}
static __device__ __forceinline__ float2 unpk(unsigned long long v) {
    float2 f;
    asm("mov.b64 {%0, %1}, %2;" : "=f"(f.x), "=f"(f.y) : "l"(v));
    return f;
}
static __device__ __forceinline__ unsigned long long packsi(float score, int idx) {
    return ((unsigned long long)__float_as_uint(score) << 32) |
           (unsigned long long)(unsigned)(~idx);
}
static __device__ __forceinline__ unsigned long long umaxll(unsigned long long a,
                                                            unsigned long long b) {
    return a > b ? a : b;
}

// ---------------------------------------------------------------------------
// Kernel 0: reset packed max arrays (graph replays must be deterministic)
// ---------------------------------------------------------------------------
__global__ void init_kernel() {
    int i = blockIdx.x * blockDim.x + threadIdx.x;
    if (i < BNprod * Tdim) {
        g_t2s[i] = INIT_PACK;
        g_s2t[i] = INIT_PACK;
    }
}

// ---------------------------------------------------------------------------
// Kernel 1: fused fp32 GEMM (f32x2 pipe) + norm + mask + threshold + dual max
// One CTA per 128x128 tile of the 256x256 sim matrix of one (b,n).
// grid.x = B*N*4, block = 256 threads, 8x8 outputs/thread (4x f32x2 x 8)
// ---------------------------------------------------------------------------
__global__ __launch_bounds__(256, 2)
void sim_gemm(const float* __restrict__ tar,   // (B, C, T)
              const float* __restrict__ src,   // (B, N, C, T)
              const float* __restrict__ srcm,  // (B, N, T)
              const float* __restrict__ tarm)  // (B, T)
{
    const int tid = threadIdx.x;
    const int blk = blockIdx.x;
    const int bn  = blk >> 2;
    const int sub = blk & 3;
    const int b   = bn >> 5;
    const int t0  = (sub >> 1) << 7;
    const int s0  = (sub & 1) << 7;

    const float* A  = tar + (size_t)b  * Cdim * Tdim;   // [C][T]
    const float* Bp = src + (size_t)bn * Cdim * Tdim;   // [C][S]

    __shared__ __align__(16) float As[8][128];
    __shared__ __align__(16) float Bs[8][128];
    __shared__ float fA[128], fB[128];                  // sumsq -> inv_norm*mask
    __shared__ unsigned long long rowp[128], colp[128];

    if (tid < 128) { fA[tid] = 0.f; rowp[tid] = 0ULL; }
    else           { fB[tid - 128] = 0.f; colp[tid - 128] = 0ULL; }

    const int r     = tid >> 5;          // k-row within 8-slice
    const int tcol  = (tid & 31) << 2;   // float4 column
    const int ty    = tid >> 4;
    const int tx    = tid & 15;
    const int trow0 = ty << 3;
    const int scol0 = tx << 3;

    unsigned long long acc[4][8];
#pragma unroll
    for (int i = 0; i < 4; i++)
#pragma unroll
        for (int j = 0; j < 8; j++) acc[i][j] = 0ULL;

    float sqa[4] = {0.f, 0.f, 0.f, 0.f};
    float sqb[4] = {0.f, 0.f, 0.f, 0.f};

    const float* Aload = A  + (size_t)r * Tdim + t0 + tcol;
    const float* Bload = Bp + (size_t)r * Tdim + s0 + tcol;

    __syncthreads();

    for (int kc = 0; kc < Cdim; kc += 8) {
        float4 av = *(const float4*)(Aload + (size_t)kc * Tdim);
        float4 bv = *(const float4*)(Bload + (size_t)kc * Tdim);
        *(float4*)&As[r][tcol] = av;
        *(float4*)&Bs[r][tcol] = bv;
        sqa[0] += av.x * av.x; sqa[1] += av.y * av.y;
        sqa[2] += av.z * av.z; sqa[3] += av.w * av.w;
        sqb[0] += bv.x * bv.x; sqb[1] += bv.y * bv.y;
        sqb[2] += bv.z * bv.z; sqb[3] += bv.w * bv.w;
        __syncthreads();

#pragma unroll
        for (int k = 0; k < 8; k++) {
            unsigned long long a2[4];
#pragma unroll
            for (int i = 0; i < 4; i++)
                a2[i] = *(const unsigned long long*)&As[k][trow0 + 2 * i];
            float4 b0 = *(const float4*)&Bs[k][scol0];
            float4 b1 = *(const float4*)&Bs[k][scol0 + 4];
            unsigned long long bd[8];
            bd[0] = dup2(b0.x); bd[1] = dup2(b0.y);
            bd[2] = dup2(b0.z); bd[3] = dup2(b0.w);
            bd[4] = dup2(b1.x); bd[5] = dup2(b1.y);
            bd[6] = dup2(b1.z); bd[7] = dup2(b1.w);
#pragma unroll
            for (int i = 0; i < 4; i++)
#pragma unroll
                for (int j = 0; j < 8; j++)
                    acc[i][j] = fma2(a2[i], bd[j], acc[i][j]);
        }
        __syncthreads();
    }

    // Fused norms: merge per-thread partial sum-of-squares
    atomicAdd(&fA[tcol + 0], sqa[0]); atomicAdd(&fA[tcol + 1], sqa[1]);
    atomicAdd(&fA[tcol + 2], sqa[2]); atomicAdd(&fA[tcol + 3], sqa[3]);
    atomicAdd(&fB[tcol + 0], sqb[0]); atomicAdd(&fB[tcol + 1], sqb[1]);
    atomicAdd(&fB[tcol + 2], sqb[2]); atomicAdd(&fB[tcol + 3], sqb[3]);
    __syncthreads();

    if (tid < 128) {
        float inv = 1.0f / fmaxf(sqrtf(fA[tid]), 1e-12f);
        fA[tid] = inv * tarm[b * Tdim + t0 + tid];
    } else {
        int s = tid - 128;
        float inv = 1.0f / fmaxf(sqrtf(fB[s]), 1e-12f);
        fB[s] = inv * srcm[bn * Tdim + s0 + s];
    }
    __syncthreads();

    // Epilogue: scale, threshold, packed dual max/argmax
    unsigned long long colc[8];
#pragma unroll
    for (int j = 0; j < 8; j++) colc[j] = 0ULL;

#pragma unroll
    for (int i = 0; i < 4; i++) {
        const int tg0 = t0 + trow0 + 2 * i;
        const int tg1 = tg0 + 1;
        const float fa0 = fA[trow0 + 2 * i];
        const float fa1 = fA[trow0 + 2 * i + 1];
        unsigned long long row0 = 0ULL, row1 = 0ULL;
#pragma unroll
        for (int j = 0; j < 8; j++) {
            float2 p = unpk(acc[i][j]);
            float fb = fB[scol0 + j];
            float v0 = p.x * fa0 * fb; if (v0 < 0.05f) v0 = 0.f;
            float v1 = p.y * fa1 * fb; if (v1 < 0.05f) v1 = 0.f;
            const int sg = s0 + scol0 + j;
            row0 = umaxll(row0, packsi(v0, sg));
            row1 = umaxll(row1, packsi(v1, sg));
            colc[j] = umaxll(colc[j], umaxll(packsi(v0, tg0), packsi(v1, tg1)));
        }
        atomicMax(&rowp[trow0 + 2 * i],     row0);
        atomicMax(&rowp[trow0 + 2 * i + 1], row1);
    }
#pragma unroll
    for (int j = 0; j < 8; j++) atomicMax(&colp[scol0 + j], colc[j]);
    __syncthreads();

    if (tid < 128) atomicMax(&g_t2s[bn * Tdim + t0 + tid], rowp[tid]);
    else           atomicMax(&g_s2t[bn * Tdim + s0 + (tid - 128)], colp[tid - 128]);
}

// ---------------------------------------------------------------------------
// Kernel 2: cycle consistency + masks + match_counts + sim_avg
// grid = B*N, block = T
// ---------------------------------------------------------------------------
__global__ void stage2(const float* __restrict__ srcm,
                       const float* __restrict__ tarm,
                       float* __restrict__ out)
{
    const int bn = blockIdx.x;
    const int b  = bn >> 5;
    const int t  = threadIdx.x;

    unsigned long long pt = g_t2s[bn * Tdim + t];
    float sc_t2s = __uint_as_float((unsigned)(pt >> 32));
    int   i_t2s  = (int)(~(unsigned)pt);

    unsigned long long pst = g_s2t[bn * Tdim + t];
    int i_s2t_here = (int)(~(unsigned)pst);

    unsigned long long psi = g_s2t[bn * Tdim + i_t2s];
    float sc_s2t_i = __uint_as_float((unsigned)(psi >> 32));
    int   i_s2s    = (int)(~(unsigned)psi);

    int dx = (i_s2s & 15) - (t & 15);
    int dy = (i_s2s >> 4) - (t >> 4);
    bool cyc  = (dx * dx + dy * dy <= 4) && (sc_s2t_i >= 0.05f);
    bool msim = (sc_t2s >= 0.05f);

    float m = 0.f;
    if (msim && cyc && i_s2t_here != 0 && i_t2s != 0)
        m = tarm[b * Tdim + t] * srcm[bn * Tdim + i_t2s];

    g_mask_all[bn * Tdim + t] = m;

    __shared__ float s1[Tdim], s2[Tdim];
    s1[t] = m;
    s2[t] = sc_t2s * m;
    __syncthreads();
    for (int off = Tdim / 2; off > 0; off >>= 1) {
        if (t < off) { s1[t] += s1[t + off]; s2[t] += s2[t + off]; }
        __syncthreads();
    }
    if (t == 0) {
        float cnt = s1[0];
        out[OFF_CNT + bn] = cnt;
        g_simavg[bn] = (cnt > 0.f) ? (s2[0] * (1.0f / 256.0f)) : 0.f;
    }
}

// ---------------------------------------------------------------------------
// Kernel 3: top-K template selection (stable ties = ascending index)
// grid = B
// ---------------------------------------------------------------------------
__global__ void stage3(float* __restrict__ out)
{
    const int b = blockIdx.x;
    if (threadIdx.x != 0) return;
    float sa[Ndim];
    bool used[Ndim];
#pragma unroll
    for (int n = 0; n < Ndim; n++) { sa[n] = g_simavg[b * Ndim + n]; used[n] = false; }
    for (int k = 0; k < KTOP; k++) {
        float best = -1.f; int bi = 0;
        for (int n = 0; n < Ndim; n++)
            if (!used[n] && sa[n] > best) { best = sa[n]; bi = n; }
        used[bi] = true;
        g_sel[b * KTOP + k] = bi;
        out[OFF_ID    + b * KTOP + k] = (float)bi;
        out[OFF_SCORE + b * KTOP + k] = best;
    }
}

// ---------------------------------------------------------------------------
// Kernel 4: format predictions for the selected templates
// grid = B*K, block = T
// ---------------------------------------------------------------------------
__global__ void stage4(float* __restrict__ out)
{
    const int bk = blockIdx.x;
    const int b  = bk / KTOP;
    const int n  = g_sel[bk];
    const int t  = threadIdx.x;
    const int bnT = (b * Ndim + n) * Tdim + t;

    unsigned long long pt = g_t2s[bnT];
    float sc = __uint_as_float((unsigned)(pt >> 32));
    int  idx = (int)(~(unsigned)pt);
    float m  = g_mask_all[bnT];

    out[OFF_SPTS + bk * Tdim + t] = sc;
    const int o = (bk * Tdim + t) * 2;
    if (m != 0.f) {
        out[OFF_TAR + o]     = (float)(t & 15);
        out[OFF_TAR + o + 1] = (float)(t >> 4);
        out[OFF_SRC + o]     = (float)(idx & 15);
        out[OFF_SRC + o + 1] = (float)(idx >> 4);
    } else {
        out[OFF_TAR + o]     = -1.f;
        out[OFF_TAR + o + 1] = -1.f;
        out[OFF_SRC + o]     = -1.f;
        out[OFF_SRC + o + 1] = -1.f;
    }
}

// ---------------------------------------------------------------------------
extern "C" void kernel_launch(void* const* d_in, const int* in_sizes, int n_in,
                              void* d_out, int out_size)
{
    const float* src  = (const float*)d_in[0];   // src_feats (B,N,C,P,P)
    const float* tar  = (const float*)d_in[1];   // tar_feat  (B,C,P,P)
    const float* srcm = (const float*)d_in[2];   // src_masks (B,N,P,P)
    const float* tarm = (const float*)d_in[3];   // tar_mask  (B,P,P)
    float* out = (float*)d_out;

    init_kernel<<<BNprod * Tdim / 256, 256>>>();
    sim_gemm<<<BNprod * 4, 256>>>(tar, src, srcm, tarm);
    stage2<<<BNprod, Tdim>>>(srcm, tarm, out);
    stage3<<<Bdim, 32>>>(out);
    stage4<<<Bdim * KTOP, Tdim>>>(out);
}

// round 2
// speedup vs baseline: 1.0010x; 1.0010x over previous
#include <cuda_runtime.h>
#include <cuda_bf16.h>

// Problem dims (fixed by reference)
#define Bdim   8
#define Ndim   32
#define Cdim   768
#define Tdim   256
#define Pdim   16
#define KTOP   5
#define BNprod (Bdim * Ndim)   // 256

// Output layout (float32, concatenated in return-tuple order)
#define OFF_ID      0            // id_src        (B,K)        = 40
#define OFF_SCORE   40           // score_src     (B,K)        = 40
#define OFF_SPTS    80           // score_pts     (B,K,T)      = 10240
#define OFF_TAR     10320        // tar_pts       (B,K,T,2)    = 20480
#define OFF_SRC     30800        // src_pts       (B,K,T,2)    = 20480
#define OFF_CNT     51280        // match_counts  (B,N)        = 256
// total 51536

// Scratch (no cudaMalloc allowed)
__device__ unsigned long long g_t2s[BNprod * Tdim];   // packed (score, ~argmax_s) per (b,n,t)
__device__ unsigned long long g_s2t[BNprod * Tdim];   // packed (score, ~argmax_t) per (b,n,s)
__device__ float              g_mask_all[BNprod * Tdim];
__device__ float              g_simavg[BNprod];
__device__ int                g_sel[Bdim * KTOP];

#define INIT_PACK 0x00000000FFFFFFFFULL   // score=0.0, idx=0

static __device__ __forceinline__ unsigned long long fma2(unsigned long long a,
                                                          unsigned long long b,
                                                          unsigned long long c) {
    unsigned long long d;
    asm("fma.rn.f32x2 %0, %1, %2, %3;" : "=l"(d) : "l"(a), "l"(b), "l"(c));
    return d;
}
static __device__ __forceinline__ unsigned long long dup2(float x) {
    unsigned long long r;
    asm("mov.b64 %0, {%1, %1};" : "=l"(r) : "f"(x));
    return r;
}
static __device__ __forceinline__ float2 unpk(unsigned long long v) {
    float2 f;
    asm("mov.b64 {%0, %1}, %2;" : "=f"(f.x), "=f"(f.y) : "l"(v));
    return f;
}
static __device__ __forceinline__ unsigned long long packsi(float score, int idx) {
    return ((unsigned long long)__float_as_uint(score) << 32) |
           (unsigned long long)(unsigned)(~idx);
}
static __device__ __forceinline__ unsigned long long umaxll(unsigned long long a,
                                                            unsigned long long b) {
    return a > b ? a : b;
}

// ---------------------------------------------------------------------------
// Kernel 0: reset packed max arrays (graph replays must be deterministic)
// ---------------------------------------------------------------------------
__global__ void init_kernel() {
    int i = blockIdx.x * blockDim.x + threadIdx.x;
    if (i < BNprod * Tdim) {
        g_t2s[i] = INIT_PACK;
        g_s2t[i] = INIT_PACK;
    }
}

// ---------------------------------------------------------------------------
// Kernel 1: fused fp32 GEMM (f32x2 pipe) + norm + mask + threshold + dual max
// One CTA per 128x128 tile of the 256x256 sim matrix of one (b,n).
// grid.x = B*N*4, block = 256 threads, 8x8 outputs/thread (4x f32x2 x 8)
// ---------------------------------------------------------------------------
__global__ __launch_bounds__(256, 2)
void sim_gemm(const float* __restrict__ tar,   // (B, C, T)
              const float* __restrict__ src,   // (B, N, C, T)
              const float* __restrict__ srcm,  // (B, N, T)
              const float* __restrict__ tarm)  // (B, T)
{
    const int tid = threadIdx.x;
    const int blk = blockIdx.x;
    const int bn  = blk >> 2;
    const int sub = blk & 3;
    const int b   = bn >> 5;
    const int t0  = (sub >> 1) << 7;
    const int s0  = (sub & 1) << 7;

    const float* A  = tar + (size_t)b  * Cdim * Tdim;   // [C][T]
    const float* Bp = src + (size_t)bn * Cdim * Tdim;   // [C][S]

    __shared__ __align__(16) float As[8][128];
    __shared__ __align__(16) float Bs[8][128];
    __shared__ float fA[128], fB[128];                  // sumsq -> inv_norm*mask
    __shared__ unsigned long long rowp[128], colp[128];

    if (tid < 128) { fA[tid] = 0.f; rowp[tid] = 0ULL; }
    else           { fB[tid - 128] = 0.f; colp[tid - 128] = 0ULL; }

    const int r     = tid >> 5;          // k-row within 8-slice
    const int tcol  = (tid & 31) << 2;   // float4 column
    const int ty    = tid >> 4;
    const int tx    = tid & 15;
    const int trow0 = ty << 3;
    const int scol0 = tx << 3;

    unsigned long long acc[4][8];
#pragma unroll
    for (int i = 0; i < 4; i++)
#pragma unroll
        for (int j = 0; j < 8; j++) acc[i][j] = 0ULL;

    float sqa[4] = {0.f, 0.f, 0.f, 0.f};
    float sqb[4] = {0.f, 0.f, 0.f, 0.f};

    const float* Aload = A  + (size_t)r * Tdim + t0 + tcol;
    const float* Bload = Bp + (size_t)r * Tdim + s0 + tcol;

    __syncthreads();

    for (int kc = 0; kc < Cdim; kc += 8) {
        float4 av = *(const float4*)(Aload + (size_t)kc * Tdim);
        float4 bv = *(const float4*)(Bload + (size_t)kc * Tdim);
        *(float4*)&As[r][tcol] = av;
        *(float4*)&Bs[r][tcol] = bv;
        sqa[0] += av.x * av.x; sqa[1] += av.y * av.y;
        sqa[2] += av.z * av.z; sqa[3] += av.w * av.w;
        sqb[0] += bv.x * bv.x; sqb[1] += bv.y * bv.y;
        sqb[2] += bv.z * bv.z; sqb[3] += bv.w * bv.w;
        __syncthreads();

#pragma unroll
        for (int k = 0; k < 8; k++) {
            unsigned long long a2[4];
#pragma unroll
            for (int i = 0; i < 4; i++)
                a2[i] = *(const unsigned long long*)&As[k][trow0 + 2 * i];
            float4 b0 = *(const float4*)&Bs[k][scol0];
            float4 b1 = *(const float4*)&Bs[k][scol0 + 4];
            unsigned long long bd[8];
            bd[0] = dup2(b0.x); bd[1] = dup2(b0.y);
            bd[2] = dup2(b0.z); bd[3] = dup2(b0.w);
            bd[4] = dup2(b1.x); bd[5] = dup2(b1.y);
            bd[6] = dup2(b1.z); bd[7] = dup2(b1.w);
#pragma unroll
            for (int i = 0; i < 4; i++)
#pragma unroll
                for (int j = 0; j < 8; j++)
                    acc[i][j] = fma2(a2[i], bd[j], acc[i][j]);
        }
        __syncthreads();
    }

    // Fused norms: merge per-thread partial sum-of-squares
    atomicAdd(&fA[tcol + 0], sqa[0]); atomicAdd(&fA[tcol + 1], sqa[1]);
    atomicAdd(&fA[tcol + 2], sqa[2]); atomicAdd(&fA[tcol + 3], sqa[3]);
    atomicAdd(&fB[tcol + 0], sqb[0]); atomicAdd(&fB[tcol + 1], sqb[1]);
    atomicAdd(&fB[tcol + 2], sqb[2]); atomicAdd(&fB[tcol + 3], sqb[3]);
    __syncthreads();

    if (tid < 128) {
        float inv = 1.0f / fmaxf(sqrtf(fA[tid]), 1e-12f);
        fA[tid] = inv * tarm[b * Tdim + t0 + tid];
    } else {
        int s = tid - 128;
        float inv = 1.0f / fmaxf(sqrtf(fB[s]), 1e-12f);
        fB[s] = inv * srcm[bn * Tdim + s0 + s];
    }
    __syncthreads();

    // Epilogue: scale, threshold, packed dual max/argmax
    unsigned long long colc[8];
#pragma unroll
    for (int j = 0; j < 8; j++) colc[j] = 0ULL;

#pragma unroll
    for (int i = 0; i < 4; i++) {
        const int tg0 = t0 + trow0 + 2 * i;
        const int tg1 = tg0 + 1;
        const float fa0 = fA[trow0 + 2 * i];
        const float fa1 = fA[trow0 + 2 * i + 1];
        unsigned long long row0 = 0ULL, row1 = 0ULL;
#pragma unroll
        for (int j = 0; j < 8; j++) {
            float2 p = unpk(acc[i][j]);
            float fb = fB[scol0 + j];
            float v0 = p.x * fa0 * fb; if (v0 < 0.05f) v0 = 0.f;
            float v1 = p.y * fa1 * fb; if (v1 < 0.05f) v1 = 0.f;
            const int sg = s0 + scol0 + j;
            row0 = umaxll(row0, packsi(v0, sg));
            row1 = umaxll(row1, packsi(v1, sg));
            colc[j] = umaxll(colc[j], umaxll(packsi(v0, tg0), packsi(v1, tg1)));
        }
        atomicMax(&rowp[trow0 + 2 * i],     row0);
        atomicMax(&rowp[trow0 + 2 * i + 1], row1);
    }
#pragma unroll
    for (int j = 0; j < 8; j++) atomicMax(&colp[scol0 + j], colc[j]);
    __syncthreads();

    if (tid < 128) atomicMax(&g_t2s[bn * Tdim + t0 + tid], rowp[tid]);
    else           atomicMax(&g_s2t[bn * Tdim + s0 + (tid - 128)], colp[tid - 128]);
}

// ---------------------------------------------------------------------------
// Kernel 2: cycle consistency + masks + match_counts + sim_avg
// grid = B*N, block = T
// ---------------------------------------------------------------------------
__global__ void stage2(const float* __restrict__ srcm,
                       const float* __restrict__ tarm,
                       float* __restrict__ out)
{
    const int bn = blockIdx.x;
    const int b  = bn >> 5;
    const int t  = threadIdx.x;

    unsigned long long pt = g_t2s[bn * Tdim + t];
    float sc_t2s = __uint_as_float((unsigned)(pt >> 32));
    int   i_t2s  = (int)(~(unsigned)pt);

    unsigned long long pst = g_s2t[bn * Tdim + t];
    int i_s2t_here = (int)(~(unsigned)pst);

    unsigned long long psi = g_s2t[bn * Tdim + i_t2s];
    float sc_s2t_i = __uint_as_float((unsigned)(psi >> 32));
    int   i_s2s    = (int)(~(unsigned)psi);

    int dx = (i_s2s & 15) - (t & 15);
    int dy = (i_s2s >> 4) - (t >> 4);
    bool cyc  = (dx * dx + dy * dy <= 4) && (sc_s2t_i >= 0.05f);
    bool msim = (sc_t2s >= 0.05f);

    float m = 0.f;
    if (msim && cyc && i_s2t_here != 0 && i_t2s != 0)
        m = tarm[b * Tdim + t] * srcm[bn * Tdim + i_t2s];

    g_mask_all[bn * Tdim + t] = m;

    __shared__ float s1[Tdim], s2[Tdim];
    s1[t] = m;
    s2[t] = sc_t2s * m;
    __syncthreads();
    for (int off = Tdim / 2; off > 0; off >>= 1) {
        if (t < off) { s1[t] += s1[t + off]; s2[t] += s2[t + off]; }
        __syncthreads();
    }
    if (t == 0) {
        float cnt = s1[0];
        out[OFF_CNT + bn] = cnt;
        g_simavg[bn] = (cnt > 0.f) ? (s2[0] * (1.0f / 256.0f)) : 0.f;
    }
}

// ---------------------------------------------------------------------------
// Kernel 3: top-K template selection (stable ties = ascending index)
// grid = B
// ---------------------------------------------------------------------------
__global__ void stage3(float* __restrict__ out)
{
    const int b = blockIdx.x;
    if (threadIdx.x != 0) return;
    float sa[Ndim];
    bool used[Ndim];
#pragma unroll
    for (int n = 0; n < Ndim; n++) { sa[n] = g_simavg[b * Ndim + n]; used[n] = false; }
    for (int k = 0; k < KTOP; k++) {
        float best = -1.f; int bi = 0;
        for (int n = 0; n < Ndim; n++)
            if (!used[n] && sa[n] > best) { best = sa[n]; bi = n; }
        used[bi] = true;
        g_sel[b * KTOP + k] = bi;
        out[OFF_ID    + b * KTOP + k] = (float)bi;
        out[OFF_SCORE + b * KTOP + k] = best;
    }
}

// ---------------------------------------------------------------------------
// Kernel 4: format predictions for the selected templates
// grid = B*K, block = T
// ---------------------------------------------------------------------------
__global__ void stage4(float* __restrict__ out)
{
    const int bk = blockIdx.x;
    const int b  = bk / KTOP;
    const int n  = g_sel[bk];
    const int t  = threadIdx.x;
    const int bnT = (b * Ndim + n) * Tdim + t;

    unsigned long long pt = g_t2s[bnT];
    float sc = __uint_as_float((unsigned)(pt >> 32));
    int  idx = (int)(~(unsigned)pt);
    float m  = g_mask_all[bnT];

    out[OFF_SPTS + bk * Tdim + t] = sc;
    const int o = (bk * Tdim + t) * 2;
    if (m != 0.f) {
        out[OFF_TAR + o]     = (float)(t & 15);
        out[OFF_TAR + o + 1] = (float)(t >> 4);
        out[OFF_SRC + o]     = (float)(idx & 15);
        out[OFF_SRC + o + 1] = (float)(idx >> 4);
    } else {
        out[OFF_TAR + o]     = -1.f;
        out[OFF_TAR + o + 1] = -1.f;
        out[OFF_SRC + o]     = -1.f;
        out[OFF_SRC + o + 1] = -1.f;
    }
}

// ---------------------------------------------------------------------------
extern "C" void kernel_launch(void* const* d_in, const int* in_sizes, int n_in,
                              void* d_out, int out_size)
{
    const float* src  = (const float*)d_in[0];   // src_feats (B,N,C,P,P)
    const float* tar  = (const float*)d_in[1];   // tar_feat  (B,C,P,P)
    const float* srcm = (const float*)d_in[2];   // src_masks (B,N,P,P)
    const float* tarm = (const float*)d_in[3];   // tar_mask  (B,P,P)
    float* out = (float*)d_out;

    init_kernel<<<BNprod * Tdim / 256, 256>>>();
    sim_gemm<<<BNprod * 4, 256>>>(tar, src, srcm, tarm);
    stage2<<<BNprod, Tdim>>>(srcm, tarm, out);
    stage3<<<Bdim, 32>>>(out);
    stage4<<<Bdim * KTOP, Tdim>>>(out);
}